// round 12
// baseline (speedup 1.0000x reference)
#include <cuda_runtime.h>
#include <cuda_bf16.h>
#include <cstdint>

// Problem constants
#define BB   8
#define NN   1024
#define CC   512
#define HH   4
#define HD   128
#define BN_TOK (BB * NN)          // 8192
#define C3  (3 * CC)              // 1536
#define SCALE 0.08838834764831845f  // 128^-0.5

#define NST 3                      // pipeline stages
#define BK  32                     // k per stage
#define APITCH 36                  // floats per row, A / B(T) tiles ([row][k]), 32+4 pad
#define BPITCH 132                 // floats per row, B(N) tiles ([k][n]); 132 mod 32 = 4
                                   // -> sigma=2tg scalar loads stay conflict-free

// Scratch (device globals: no allocation allowed)
__device__ float g_qkv[(size_t)BN_TOK * C3];          // [B*N, 3C]  tf32-rounded
__device__ float g_s[(size_t)BB * HH * NN * NN];      // [B,H,N,N]  (in-place P)
__device__ float g_o[(size_t)BN_TOK * CC];            // [B,N,C]    tf32-rounded
__device__ float g_xr[(size_t)BN_TOK * CC];           // x  tf32-rounded
__device__ float g_wqkvr[(size_t)C3 * CC];            // w_qkv tf32-rounded
__device__ float g_wprojr[(size_t)CC * CC];           // w_proj tf32-rounded

__device__ __forceinline__ unsigned f2tf32(float x) {
    unsigned r;
    asm("cvt.rna.tf32.f32 %0, %1;" : "=r"(r) : "f"(x));
    return r;
}
__device__ __forceinline__ float rndtf(float x) { return __uint_as_float(f2tf32(x)); }

__device__ __forceinline__ void mma_tf32(float* c, const unsigned* a, const unsigned* b) {
    asm volatile(
        "mma.sync.aligned.m16n8k8.row.col.f32.tf32.tf32.f32 "
        "{%0,%1,%2,%3}, {%4,%5,%6,%7}, {%8,%9}, {%0,%1,%2,%3};"
        : "+f"(c[0]), "+f"(c[1]), "+f"(c[2]), "+f"(c[3])
        : "r"(a[0]), "r"(a[1]), "r"(a[2]), "r"(a[3]), "r"(b[0]), "r"(b[1]));
}

__device__ __forceinline__ void cp16(unsigned dst, const void* src) {
    asm volatile("cp.async.cg.shared.global [%0], [%1], 16;" :: "r"(dst), "l"(src));
}
__device__ __forceinline__ void cp_commit() {
    asm volatile("cp.async.commit_group;");
}
__device__ __forceinline__ void cp_wait() {
    asm volatile("cp.async.wait_group %0;" :: "n"(NST - 2));
}

// ---------------------------------------------------------------------------
// tf32 round prepass: out[i] = tf32(in[i]), float4-wide
// ---------------------------------------------------------------------------
__global__ __launch_bounds__(256) void round_kernel(
    const float* __restrict__ in, float* __restrict__ out, int n4)
{
    int i = blockIdx.x * 256 + threadIdx.x;
    if (i < n4) {
        float4 v = ((const float4*)in)[i];
        v.x = rndtf(v.x); v.y = rndtf(v.y);
        v.z = rndtf(v.z); v.w = rndtf(v.w);
        ((float4*)out)[i] = v;
    }
}

// ---------------------------------------------------------------------------
// tf32 tensor-core GEMM, cp.async 3-stage pipeline, BK=32/stage, one barrier
// per stage, 2 CTAs/SM. k-slot permutation sigma: HW slots (tg, tg+4) are fed
// logical k = (2tg, 2tg+1), identically for A and B -> fragment pair loads
// become one LDS.64 (A always; B in TRANSB case). Sum over k is permutation-
// invariant, so results are unchanged up to intra-mma accumulation order.
//   C = alpha * A (.) op(B) (+ bias) [, tf32-rounded output if RND]
//   TRANSB=true : B is [N,K] row-major (C = A B^T)
//   TRANSB=false: B is [K,N] row-major (C = A B)
// CTA tile 128x128, 256 threads = 8 warps, warp tile 32x64.
// ---------------------------------------------------------------------------
template<bool TRANSB, bool BIAS, bool RND>
__global__ __launch_bounds__(256, 2) void tgemm_kernel(
    const float* __restrict__ A, const float* __restrict__ B,
    float* __restrict__ C, const float* __restrict__ bias,
    int K, int lda, int ldb, int ldc,
    int bin,
    long long sAi, long long sAo,
    long long sBi, long long sBo,
    long long sCi, long long sCo,
    float alpha)
{
    int z  = blockIdx.z;
    int zi = z % bin, zo = z / bin;
    A += (size_t)zi * sAi + (size_t)zo * sAo;
    B += (size_t)zi * sBi + (size_t)zo * sBo;
    C += (size_t)zi * sCi + (size_t)zo * sCo;

    extern __shared__ float smp[];
    float* AsAll = smp;                                   // [NST][128][APITCH]
    float* BsAll = smp + NST * 128 * APITCH;              // T:[NST][128][APITCH] N:[NST][32][BPITCH]
    const int BSTG = TRANSB ? 128 * APITCH : 32 * BPITCH;

    const int tid  = threadIdx.x;
    const int lane = tid & 31;
    const int g    = lane >> 2;
    const int tg   = lane & 3;
    const int wm   = (tid >> 5) & 3;
    const int wn   = tid >> 7;
    const int mbase = wm * 32;
    const int nbase = wn * 64;

    const int rowBase = blockIdx.y * 128;
    const int colBase = blockIdx.x * 128;

    float acc[2][8][4];
    #pragma unroll
    for (int mi = 0; mi < 2; mi++)
        #pragma unroll
        for (int ni = 0; ni < 8; ni++)
            #pragma unroll
            for (int r = 0; r < 4; r++) acc[mi][ni][r] = 0.0f;

    // ---- stage loader: A 128x32, B 128x32 (T) or 32x128 (N) ----
    auto loadStage = [&](int st, int kt) {
        float* Ad = AsAll + st * 128 * APITCH;
        #pragma unroll
        for (int r = 0; r < 4; r++) {
            int c   = r * 256 + tid;
            int row = c >> 3;                // 8 chunks per 32-float row
            int kq  = (c & 7) << 2;
            cp16((unsigned)__cvta_generic_to_shared(Ad + row * APITCH + kq),
                 A + (size_t)(rowBase + row) * lda + kt + kq);
        }
        float* Bd = BsAll + st * BSTG;
        if (TRANSB) {
            #pragma unroll
            for (int r = 0; r < 4; r++) {
                int c   = r * 256 + tid;
                int row = c >> 3;
                int kq  = (c & 7) << 2;
                cp16((unsigned)__cvta_generic_to_shared(Bd + row * APITCH + kq),
                     B + (size_t)(colBase + row) * ldb + kt + kq);
            }
        } else {
            #pragma unroll
            for (int r = 0; r < 4; r++) {
                int c    = r * 256 + tid;
                int krow = c >> 5;           // 32 chunks per 128-float row
                int nq   = (c & 31) << 2;
                cp16((unsigned)__cvta_generic_to_shared(Bd + krow * BPITCH + nq),
                     B + (size_t)(kt + krow) * ldb + colBase + nq);
            }
        }
    };

    const int nk = K >> 5;   // 32-k stages
    loadStage(0, 0);
    cp_commit();
    if (nk > 1) loadStage(1, BK);
    cp_commit();

    int st = 0;
    for (int it = 0; it < nk; it++) {
        cp_wait();
        __syncthreads();     // stage `st` complete+visible; all warps done reading
                             // the stage about to be overwritten below (WAR safe)

        int ktn = (it + NST - 1) << 5;
        int stn = st + NST - 1; if (stn >= NST) stn -= NST;
        if (ktn < K) loadStage(stn, ktn);
        cp_commit();

        const float* Asb = AsAll + st * 128 * APITCH;
        const float* Bsb = BsAll + st * BSTG;
        #pragma unroll
        for (int ks = 0; ks < BK; ks += 8) {
            unsigned a[2][4], b[8][2];
            #pragma unroll
            for (int mi = 0; mi < 2; mi++) {
                int m = mbase + mi * 16 + g;
                // sigma: slot0 <- k=2tg, slot1 <- k=2tg+1 (contiguous -> LDS.64)
                float2 a0 = *(const float2*)(Asb + (size_t)m * APITCH + ks + 2 * tg);
                float2 a1 = *(const float2*)(Asb + (size_t)(m + 8) * APITCH + ks + 2 * tg);
                a[mi][0] = __float_as_uint(a0.x);
                a[mi][2] = __float_as_uint(a0.y);
                a[mi][1] = __float_as_uint(a1.x);
                a[mi][3] = __float_as_uint(a1.y);
            }
            #pragma unroll
            for (int ni = 0; ni < 8; ni++) {
                int n = nbase + ni * 8 + g;
                if (TRANSB) {
                    float2 b0 = *(const float2*)(Bsb + (size_t)n * APITCH + ks + 2 * tg);
                    b[ni][0] = __float_as_uint(b0.x);
                    b[ni][1] = __float_as_uint(b0.y);
                } else {
                    b[ni][0] = __float_as_uint(Bsb[(size_t)(ks + 2 * tg) * BPITCH + n]);
                    b[ni][1] = __float_as_uint(Bsb[(size_t)(ks + 2 * tg + 1) * BPITCH + n]);
                }
            }
            #pragma unroll
            for (int mi = 0; mi < 2; mi++)
                #pragma unroll
                for (int ni = 0; ni < 8; ni++)
                    mma_tf32(acc[mi][ni], a[mi], b[ni]);
        }

        st++; if (st >= NST) st = 0;
        // no trailing barrier: next iteration's top barrier provides WAR + visibility
    }

    // ---- Epilogue ----
    #pragma unroll
    for (int mi = 0; mi < 2; mi++) {
        #pragma unroll
        for (int ni = 0; ni < 8; ni++) {
            int row = rowBase + mbase + mi * 16 + g;
            int col = colBase + nbase + ni * 8 + tg * 2;
            float bx = 0.f, by = 0.f;
            if (BIAS) { bx = bias[col]; by = bias[col + 1]; }
            float2 v0, v1;
            v0.x = alpha * acc[mi][ni][0] + bx;
            v0.y = alpha * acc[mi][ni][1] + by;
            v1.x = alpha * acc[mi][ni][2] + bx;
            v1.y = alpha * acc[mi][ni][3] + by;
            if (RND) {
                v0.x = rndtf(v0.x); v0.y = rndtf(v0.y);
                v1.x = rndtf(v1.x); v1.y = rndtf(v1.y);
            }
            *(float2*)(C + (size_t)row * ldc + col)       = v0;
            *(float2*)(C + (size_t)(row + 8) * ldc + col) = v1;
        }
    }
}

// ---------------------------------------------------------------------------
// Cross-head mix + softmax, in-place over g_s. Elementwise mix in registers,
// 3 barriers, float4 I/O. One CTA per (b, n), 256 threads.
// ---------------------------------------------------------------------------
__global__ __launch_bounds__(256) void mix_softmax_kernel(
    float* __restrict__ S,
    const float* __restrict__ w_main,
    const float* __restrict__ w_rest)
{
    __shared__ float Mm[16];
    __shared__ float redA[4][8];
    __shared__ float redB[4][8];

    const int b    = blockIdx.x / NN;
    const int n    = blockIdx.x % NN;
    const int tid  = threadIdx.x;
    const int lane = tid & 31;
    const int wrp  = tid >> 5;

    if (tid < 16) {
        int i = tid >> 2, j = tid & 3;
        Mm[tid] = (i == j) ? w_main[i]
                           : w_rest[i * (HH - 1) + (j < i ? j : j - 1)];
    }
    __syncthreads();

    const size_t base = ((size_t)b * HH * NN + n) * NN + tid * 4;

    float4 sv[HH];
    #pragma unroll
    for (int h = 0; h < HH; h++)
        sv[h] = *(const float4*)(S + base + (size_t)h * NN * NN);

    float4 v[HH];
    float mx[HH];
    #pragma unroll
    for (int i = 0; i < HH; i++) {
        float m0 = Mm[i*4+0], m1 = Mm[i*4+1], m2 = Mm[i*4+2], m3 = Mm[i*4+3];
        v[i].x = m0*sv[0].x + m1*sv[1].x + m2*sv[2].x + m3*sv[3].x;
        v[i].y = m0*sv[0].y + m1*sv[1].y + m2*sv[2].y + m3*sv[3].y;
        v[i].z = m0*sv[0].z + m1*sv[1].z + m2*sv[2].z + m3*sv[3].z;
        v[i].w = m0*sv[0].w + m1*sv[1].w + m2*sv[2].w + m3*sv[3].w;
        mx[i] = fmaxf(fmaxf(v[i].x, v[i].y), fmaxf(v[i].z, v[i].w));
        #pragma unroll
        for (int o = 16; o > 0; o >>= 1)
            mx[i] = fmaxf(mx[i], __shfl_xor_sync(0xffffffffu, mx[i], o));
    }
    if (lane == 0) {
        #pragma unroll
        for (int i = 0; i < HH; i++) redA[i][wrp] = mx[i];
    }
    __syncthreads();

    float sm[HH];
    #pragma unroll
    for (int i = 0; i < HH; i++) {
        float rmax = redA[i][0];
        #pragma unroll
        for (int w = 1; w < 8; w++) rmax = fmaxf(rmax, redA[i][w]);
        v[i].x = __expf(v[i].x - rmax);
        v[i].y = __expf(v[i].y - rmax);
        v[i].z = __expf(v[i].z - rmax);
        v[i].w = __expf(v[i].w - rmax);
        sm[i] = (v[i].x + v[i].y) + (v[i].z + v[i].w);
        #pragma unroll
        for (int o = 16; o > 0; o >>= 1)
            sm[i] += __shfl_xor_sync(0xffffffffu, sm[i], o);
    }
    if (lane == 0) {
        #pragma unroll
        for (int i = 0; i < HH; i++) redB[i][wrp] = sm[i];
    }
    __syncthreads();

    #pragma unroll
    for (int i = 0; i < HH; i++) {
        float rsum = redB[i][0];
        #pragma unroll
        for (int w = 1; w < 8; w++) rsum += redB[i][w];
        float inv = 1.0f / rsum;
        float4 o;
        o.x = rndtf(v[i].x * inv);
        o.y = rndtf(v[i].y * inv);
        o.z = rndtf(v[i].z * inv);
        o.w = rndtf(v[i].w * inv);
        *(float4*)(S + base + (size_t)i * NN * NN) = o;
    }
}

// ---------------------------------------------------------------------------
extern "C" void kernel_launch(void* const* d_in, const int* in_sizes, int n_in,
                              void* d_out, int out_size)
{
    const float* x      = (const float*)d_in[0];  // [B,N,C]
    const float* w_qkv  = (const float*)d_in[1];  // [3C,C]
    const float* w_proj = (const float*)d_in[2];  // [C,C]
    const float* b_proj = (const float*)d_in[3];  // [C]
    const float* w_main = (const float*)d_in[4];  // [H]
    const float* w_rest = (const float*)d_in[5];  // [H,H-1]
    float* out = (float*)d_out;                   // [B,N,C]

    float* qkv; cudaGetSymbolAddress((void**)&qkv, g_qkv);
    float* S;   cudaGetSymbolAddress((void**)&S,   g_s);
    float* O;   cudaGetSymbolAddress((void**)&O,   g_o);
    float* xr;  cudaGetSymbolAddress((void**)&xr,  g_xr);
    float* wq;  cudaGetSymbolAddress((void**)&wq,  g_wqkvr);
    float* wp;  cudaGetSymbolAddress((void**)&wp,  g_wprojr);

    const int SMEM_T = NST * (128 * APITCH * 2) * 4;              // 110592 B
    const int SMEM_N = NST * (128 * APITCH + 32 * BPITCH) * 4;    // 105984 B
    cudaFuncSetAttribute(tgemm_kernel<true,  false, true >,
                         cudaFuncAttributeMaxDynamicSharedMemorySize, SMEM_T);
    cudaFuncSetAttribute(tgemm_kernel<true,  false, false>,
                         cudaFuncAttributeMaxDynamicSharedMemorySize, SMEM_T);
    cudaFuncSetAttribute(tgemm_kernel<false, false, true >,
                         cudaFuncAttributeMaxDynamicSharedMemorySize, SMEM_N);
    cudaFuncSetAttribute(tgemm_kernel<true,  true,  false>,
                         cudaFuncAttributeMaxDynamicSharedMemorySize, SMEM_T);

    // 0) tf32-round inputs into scratch
    round_kernel<<<(BN_TOK * CC / 4) / 256, 256>>>(x, xr, BN_TOK * CC / 4);
    round_kernel<<<(C3 * CC / 4) / 256, 256>>>(w_qkv, wq, C3 * CC / 4);
    round_kernel<<<(CC * CC / 4) / 256, 256>>>(w_proj, wp, CC * CC / 4);

    // 1) QKV = Xr @ Wqkv_r^T  (output tf32-rounded)
    tgemm_kernel<true, false, true><<<dim3(C3 / 128, BN_TOK / 128, 1), 256, SMEM_T>>>(
        xr, wq, qkv, nullptr,
        CC, CC, CC, C3,
        1, 0, 0, 0, 0, 0, 0, 1.0f);

    // 2) S[b,h] = scale * Q_bh @ K_bh^T : 32 x [1024,1024,128]
    tgemm_kernel<true, false, false><<<dim3(NN / 128, NN / 128, BB * HH), 256, SMEM_T>>>(
        qkv, qkv + CC, S, nullptr,
        HD, C3, C3, NN,
        HH,
        /*sAi*/ HD, /*sAo*/ (long long)NN * C3,
        /*sBi*/ HD, /*sBo*/ (long long)NN * C3,
        /*sCi*/ (long long)NN * NN, /*sCo*/ (long long)HH * NN * NN,
        SCALE);

    // 3) cross-head mix + softmax (in-place, P tf32-rounded)
    mix_softmax_kernel<<<BB * NN, 256>>>(S, w_main, w_rest);

    // 4) O[b,h] = P_bh @ V_bh : 32 x [1024,128,1024] (output tf32-rounded)
    tgemm_kernel<false, false, true><<<dim3(HD / 128, NN / 128, BB * HH), 256, SMEM_N>>>(
        S, qkv + 2 * CC, O, nullptr,
        NN, NN, C3, CC,
        HH,
        /*sAi*/ (long long)NN * NN, /*sAo*/ (long long)HH * NN * NN,
        /*sBi*/ HD, /*sBo*/ (long long)NN * C3,
        /*sCi*/ HD, /*sCo*/ (long long)NN * CC,
        1.0f);

    // 5) out = O @ Wproj_r^T + b : [8192,512,512] (full fp32 output)
    tgemm_kernel<true, true, false><<<dim3(CC / 128, BN_TOK / 128, 1), 256, SMEM_T>>>(
        O, wp, out, b_proj,
        CC, CC, CC, CC,
        1, 0, 0, 0, 0, 0, 0, 1.0f);
}

// round 14
// speedup vs baseline: 1.6054x; 1.6054x over previous
#include <cuda_runtime.h>
#include <cuda_fp16.h>
#include <cstdint>

// Problem constants
#define BB   8
#define NN   1024
#define CC   512
#define HH   4
#define HD   128
#define BN_TOK (BB * NN)          // 8192
#define C3  (3 * CC)              // 1536
#define SCALE 0.08838834764831845f  // 128^-0.5

#define NST 3                      // pipeline stages
#define BK  32                     // k (halves) per stage
#define HPITCH 40                  // halves per row in smem tiles (32 + 8 pad)
#define STGH (128 * HPITCH)        // halves per operand stage
#define SMEM_BYTES (NST * 2 * STGH * 2)   // 61440

// Scratch (device globals: no allocation allowed)
__device__ __half g_qkvh[(size_t)BN_TOK * C3];        // QKV, fp16
__device__ float  g_s[(size_t)BB * HH * NN * NN];     // S scores fp32
__device__ __half g_p[(size_t)BB * HH * NN * NN];     // P = softmax(mix(S)), fp16
__device__ __half g_oh[(size_t)BN_TOK * CC];          // attention out, fp16
__device__ __half g_xh[(size_t)BN_TOK * CC];          // x fp16
__device__ __half g_wqh[(size_t)C3 * CC];             // w_qkv fp16
__device__ __half g_wph[(size_t)CC * CC];             // w_proj fp16
__device__ __half g_vth[(size_t)BB * HH * HD * NN];   // V transposed [bh][d][m], fp16

__device__ __forceinline__ void mma_f16(float* c, const unsigned* a, const unsigned* b) {
    asm volatile(
        "mma.sync.aligned.m16n8k16.row.col.f32.f16.f16.f32 "
        "{%0,%1,%2,%3}, {%4,%5,%6,%7}, {%8,%9}, {%0,%1,%2,%3};"
        : "+f"(c[0]), "+f"(c[1]), "+f"(c[2]), "+f"(c[3])
        : "r"(a[0]), "r"(a[1]), "r"(a[2]), "r"(a[3]), "r"(b[0]), "r"(b[1]));
}

__device__ __forceinline__ void cp16(unsigned dst, const void* src) {
    asm volatile("cp.async.cg.shared.global [%0], [%1], 16;" :: "r"(dst), "l"(src));
}
__device__ __forceinline__ void cp_commit() {
    asm volatile("cp.async.commit_group;");
}
__device__ __forceinline__ void cp_wait() {
    asm volatile("cp.async.wait_group %0;" :: "n"(NST - 2));
}

// ---------------------------------------------------------------------------
// fp16 convert prepass: out[i] = half(in[i]), float4 -> half4
// ---------------------------------------------------------------------------
__global__ __launch_bounds__(256) void tohalf_kernel(
    const float* __restrict__ in, __half* __restrict__ out, int n4)
{
    int i = blockIdx.x * 256 + threadIdx.x;
    if (i < n4) {
        float4 v = ((const float4*)in)[i];
        __half2 h0 = __floats2half2_rn(v.x, v.y);
        __half2 h1 = __floats2half2_rn(v.z, v.w);
        ((__half2*)out)[i * 2]     = h0;
        ((__half2*)out)[i * 2 + 1] = h1;
    }
}

// ---------------------------------------------------------------------------
// V transpose (half): vt[bh][d][m] = qkv_h[(b*N+m)*C3 + 2C + h*HD + d]
// grid (NN/32, HD/32, B*H), 256 threads (32x8), 32x32 half tile
// ---------------------------------------------------------------------------
__global__ __launch_bounds__(256) void vtrans_kernel(
    const __half* __restrict__ qkv, __half* __restrict__ vt)
{
    __shared__ __half t[32][34];
    const int bh = blockIdx.z;
    const int b = bh / HH, h = bh % HH;
    const int m0 = blockIdx.x * 32;
    const int d0 = blockIdx.y * 32;
    const int lx = threadIdx.x & 31, ly = threadIdx.x >> 5;

    const __half* src = qkv + (size_t)b * NN * C3 + 2 * CC + h * HD;
    #pragma unroll
    for (int r = 0; r < 4; r++) {
        int m = m0 + ly + r * 8;
        t[ly + r * 8][lx] = src[(size_t)m * C3 + d0 + lx];
    }
    __syncthreads();
    __half* dst = vt + (size_t)bh * HD * NN;
    #pragma unroll
    for (int r = 0; r < 4; r++) {
        int d = d0 + ly + r * 8;
        dst[(size_t)d * NN + m0 + lx] = t[lx][ly + r * 8];
    }
}

// ---------------------------------------------------------------------------
// fp16 tensor-core GEMM (m16n8k16), cp.async 3-stage pipeline, BK=32/stage,
// one barrier per stage, 2 CTAs/SM. Both operands K-major:
//   C[m][n] = alpha * sum_k A[m][k] * B[n][k]  (+ bias)
// CTA tile 128x128, 256 threads = 8 warps, warp tile 32x64
// (2 m-frags x 8 n-frags of m16n8k16). fp32 accumulation.
// Smem tiles [row][k], pitch 40 halves -> fragment loads are 32-bit LDS,
// banks (20g+tg) mod 32 all distinct (conflict-free).
// ---------------------------------------------------------------------------
template<bool HALF_OUT, bool BIAS>
__global__ __launch_bounds__(256, 2) void hgemm_kernel(
    const __half* __restrict__ A, const __half* __restrict__ B,
    void* __restrict__ Cv, const float* __restrict__ bias,
    int K, int lda, int ldb, int ldc,
    int bin,
    long long sAi, long long sAo,
    long long sBi, long long sBo,
    long long sCi, long long sCo,
    float alpha)
{
    int z  = blockIdx.z;
    int zi = z % bin, zo = z / bin;
    A += (size_t)zi * sAi + (size_t)zo * sAo;
    B += (size_t)zi * sBi + (size_t)zo * sBo;

    extern __shared__ __half smph[];
    __half* AsAll = smph;                 // [NST][128][HPITCH]
    __half* BsAll = smph + NST * STGH;    // [NST][128][HPITCH]

    const int tid  = threadIdx.x;
    const int lane = tid & 31;
    const int g    = lane >> 2;
    const int tg   = lane & 3;
    const int wm   = (tid >> 5) & 3;
    const int wn   = tid >> 7;
    const int mbase = wm * 32;
    const int nbase = wn * 64;

    const int rowBase = blockIdx.y * 128;
    const int colBase = blockIdx.x * 128;

    float acc[2][8][4];
    #pragma unroll
    for (int mi = 0; mi < 2; mi++)
        #pragma unroll
        for (int ni = 0; ni < 8; ni++)
            #pragma unroll
            for (int r = 0; r < 4; r++) acc[mi][ni][r] = 0.0f;

    // stage loader: 128 rows x 32 halves (64B) per operand = 4 cp16/row
    auto loadStage = [&](int st, int kt) {
        __half* Ad = AsAll + st * STGH;
        #pragma unroll
        for (int r = 0; r < 2; r++) {
            int c   = r * 256 + tid;
            int row = c >> 2;
            int ch  = (c & 3) << 3;       // 0,8,16,24 halves
            cp16((unsigned)__cvta_generic_to_shared(Ad + row * HPITCH + ch),
                 A + (size_t)(rowBase + row) * lda + kt + ch);
        }
        __half* Bd = BsAll + st * STGH;
        #pragma unroll
        for (int r = 0; r < 2; r++) {
            int c   = r * 256 + tid;
            int row = c >> 2;
            int ch  = (c & 3) << 3;
            cp16((unsigned)__cvta_generic_to_shared(Bd + row * HPITCH + ch),
                 B + (size_t)(colBase + row) * ldb + kt + ch);
        }
    };

    const int nk = K >> 5;   // 32-half stages
    loadStage(0, 0);
    cp_commit();
    if (nk > 1) loadStage(1, BK);
    cp_commit();

    int st = 0;
    for (int it = 0; it < nk; it++) {
        cp_wait();
        __syncthreads();     // stage `st` complete+visible; prior reads of the
                             // stage about to be refilled are done (WAR safe)

        int ktn = (it + NST - 1) << 5;
        int stn = st + NST - 1; if (stn >= NST) stn -= NST;
        if (ktn < K) loadStage(stn, ktn);
        cp_commit();

        const __half* Asb = AsAll + st * STGH;
        const __half* Bsb = BsAll + st * STGH;
        #pragma unroll
        for (int ks = 0; ks < BK; ks += 16) {
            unsigned a[2][4], b[8][2];
            #pragma unroll
            for (int mi = 0; mi < 2; mi++) {
                int m = mbase + mi * 16 + g;
                a[mi][0] = *(const unsigned*)(Asb + (size_t)m * HPITCH + ks + 2 * tg);
                a[mi][1] = *(const unsigned*)(Asb + (size_t)(m + 8) * HPITCH + ks + 2 * tg);
                a[mi][2] = *(const unsigned*)(Asb + (size_t)m * HPITCH + ks + 2 * tg + 8);
                a[mi][3] = *(const unsigned*)(Asb + (size_t)(m + 8) * HPITCH + ks + 2 * tg + 8);
            }
            #pragma unroll
            for (int ni = 0; ni < 8; ni++) {
                int n = nbase + ni * 8 + g;
                b[ni][0] = *(const unsigned*)(Bsb + (size_t)n * HPITCH + ks + 2 * tg);
                b[ni][1] = *(const unsigned*)(Bsb + (size_t)n * HPITCH + ks + 2 * tg + 8);
            }
            #pragma unroll
            for (int mi = 0; mi < 2; mi++)
                #pragma unroll
                for (int ni = 0; ni < 8; ni++)
                    mma_f16(acc[mi][ni], a[mi], b[ni]);
        }

        st++; if (st >= NST) st = 0;
    }

    // ---- Epilogue ----
    if (HALF_OUT) {
        __half* C = (__half*)Cv + (size_t)zi * sCi + (size_t)zo * sCo;
        #pragma unroll
        for (int mi = 0; mi < 2; mi++) {
            #pragma unroll
            for (int ni = 0; ni < 8; ni++) {
                int row = rowBase + mbase + mi * 16 + g;
                int col = colBase + nbase + ni * 8 + tg * 2;
                __half2 h0 = __floats2half2_rn(alpha * acc[mi][ni][0],
                                               alpha * acc[mi][ni][1]);
                __half2 h1 = __floats2half2_rn(alpha * acc[mi][ni][2],
                                               alpha * acc[mi][ni][3]);
                *(__half2*)(C + (size_t)row * ldc + col)       = h0;
                *(__half2*)(C + (size_t)(row + 8) * ldc + col) = h1;
            }
        }
    } else {
        float* C = (float*)Cv + (size_t)zi * sCi + (size_t)zo * sCo;
        #pragma unroll
        for (int mi = 0; mi < 2; mi++) {
            #pragma unroll
            for (int ni = 0; ni < 8; ni++) {
                int row = rowBase + mbase + mi * 16 + g;
                int col = colBase + nbase + ni * 8 + tg * 2;
                float bx = 0.f, by = 0.f;
                if (BIAS) { bx = bias[col]; by = bias[col + 1]; }
                float2 v0, v1;
                v0.x = alpha * acc[mi][ni][0] + bx;
                v0.y = alpha * acc[mi][ni][1] + by;
                v1.x = alpha * acc[mi][ni][2] + bx;
                v1.y = alpha * acc[mi][ni][3] + by;
                *(float2*)(C + (size_t)row * ldc + col)       = v0;
                *(float2*)(C + (size_t)(row + 8) * ldc + col) = v1;
            }
        }
    }
}

// ---------------------------------------------------------------------------
// Cross-head mix + softmax: reads S fp32, writes P fp16.
// One CTA per (b, n), 256 threads, 3 barriers, elementwise mix in registers.
// ---------------------------------------------------------------------------
__global__ __launch_bounds__(256) void mix_softmax_kernel(
    const float* __restrict__ S, __half* __restrict__ P,
    const float* __restrict__ w_main,
    const float* __restrict__ w_rest)
{
    __shared__ float Mm[16];
    __shared__ float redA[4][8];
    __shared__ float redB[4][8];

    const int b    = blockIdx.x / NN;
    const int n    = blockIdx.x % NN;
    const int tid  = threadIdx.x;
    const int lane = tid & 31;
    const int wrp  = tid >> 5;

    if (tid < 16) {
        int i = tid >> 2, j = tid & 3;
        Mm[tid] = (i == j) ? w_main[i]
                           : w_rest[i * (HH - 1) + (j < i ? j : j - 1)];
    }
    __syncthreads();

    const size_t base = ((size_t)b * HH * NN + n) * NN + tid * 4;

    float4 sv[HH];
    #pragma unroll
    for (int h = 0; h < HH; h++)
        sv[h] = *(const float4*)(S + base + (size_t)h * NN * NN);

    float4 v[HH];
    float mx[HH];
    #pragma unroll
    for (int i = 0; i < HH; i++) {
        float m0 = Mm[i*4+0], m1 = Mm[i*4+1], m2 = Mm[i*4+2], m3 = Mm[i*4+3];
        v[i].x = m0*sv[0].x + m1*sv[1].x + m2*sv[2].x + m3*sv[3].x;
        v[i].y = m0*sv[0].y + m1*sv[1].y + m2*sv[2].y + m3*sv[3].y;
        v[i].z = m0*sv[0].z + m1*sv[1].z + m2*sv[2].z + m3*sv[3].z;
        v[i].w = m0*sv[0].w + m1*sv[1].w + m2*sv[2].w + m3*sv[3].w;
        mx[i] = fmaxf(fmaxf(v[i].x, v[i].y), fmaxf(v[i].z, v[i].w));
        #pragma unroll
        for (int o = 16; o > 0; o >>= 1)
            mx[i] = fmaxf(mx[i], __shfl_xor_sync(0xffffffffu, mx[i], o));
    }
    if (lane == 0) {
        #pragma unroll
        for (int i = 0; i < HH; i++) redA[i][wrp] = mx[i];
    }
    __syncthreads();

    float sm[HH];
    #pragma unroll
    for (int i = 0; i < HH; i++) {
        float rmax = redA[i][0];
        #pragma unroll
        for (int w = 1; w < 8; w++) rmax = fmaxf(rmax, redA[i][w]);
        v[i].x = __expf(v[i].x - rmax);
        v[i].y = __expf(v[i].y - rmax);
        v[i].z = __expf(v[i].z - rmax);
        v[i].w = __expf(v[i].w - rmax);
        sm[i] = (v[i].x + v[i].y) + (v[i].z + v[i].w);
        #pragma unroll
        for (int o = 16; o > 0; o >>= 1)
            sm[i] += __shfl_xor_sync(0xffffffffu, sm[i], o);
    }
    if (lane == 0) {
        #pragma unroll
        for (int i = 0; i < HH; i++) redB[i][wrp] = sm[i];
    }
    __syncthreads();

    #pragma unroll
    for (int i = 0; i < HH; i++) {
        float rsum = redB[i][0];
        #pragma unroll
        for (int w = 1; w < 8; w++) rsum += redB[i][w];
        float inv = 1.0f / rsum;
        __half2 h0 = __floats2half2_rn(v[i].x * inv, v[i].y * inv);
        __half2 h1 = __floats2half2_rn(v[i].z * inv, v[i].w * inv);
        __half2* dst = (__half2*)(P + base + (size_t)i * NN * NN);
        dst[0] = h0;
        dst[1] = h1;
    }
}

// ---------------------------------------------------------------------------
extern "C" void kernel_launch(void* const* d_in, const int* in_sizes, int n_in,
                              void* d_out, int out_size)
{
    const float* x      = (const float*)d_in[0];  // [B,N,C]
    const float* w_qkv  = (const float*)d_in[1];  // [3C,C]
    const float* w_proj = (const float*)d_in[2];  // [C,C]
    const float* b_proj = (const float*)d_in[3];  // [C]
    const float* w_main = (const float*)d_in[4];  // [H]
    const float* w_rest = (const float*)d_in[5];  // [H,H-1]
    float* out = (float*)d_out;                   // [B,N,C]

    __half* qkvh; cudaGetSymbolAddress((void**)&qkvh, g_qkvh);
    float*  S;    cudaGetSymbolAddress((void**)&S,    g_s);
    __half* P;    cudaGetSymbolAddress((void**)&P,    g_p);
    __half* Oh;   cudaGetSymbolAddress((void**)&Oh,   g_oh);
    __half* xh;   cudaGetSymbolAddress((void**)&xh,   g_xh);
    __half* wqh;  cudaGetSymbolAddress((void**)&wqh,  g_wqh);
    __half* wph;  cudaGetSymbolAddress((void**)&wph,  g_wph);
    __half* vth;  cudaGetSymbolAddress((void**)&vth,  g_vth);

    cudaFuncSetAttribute(hgemm_kernel<true,  false>,
                         cudaFuncAttributeMaxDynamicSharedMemorySize, SMEM_BYTES);
    cudaFuncSetAttribute(hgemm_kernel<false, false>,
                         cudaFuncAttributeMaxDynamicSharedMemorySize, SMEM_BYTES);
    cudaFuncSetAttribute(hgemm_kernel<false, true >,
                         cudaFuncAttributeMaxDynamicSharedMemorySize, SMEM_BYTES);

    // 0) fp16 convert inputs
    tohalf_kernel<<<(BN_TOK * CC / 4) / 256, 256>>>(x, xh, BN_TOK * CC / 4);
    tohalf_kernel<<<(C3 * CC / 4) / 256, 256>>>(w_qkv, wqh, C3 * CC / 4);
    tohalf_kernel<<<(CC * CC / 4) / 256, 256>>>(w_proj, wph, CC * CC / 4);

    // 1) QKV = Xh @ Wqkv_h^T : [8192,1536,512], fp16 out
    hgemm_kernel<true, false><<<dim3(C3 / 128, BN_TOK / 128, 1), 256, SMEM_BYTES>>>(
        xh, wqh, qkvh, nullptr,
        CC, CC, CC, C3,
        1, 0, 0, 0, 0, 0, 0, 1.0f);

    // 1b) transpose V (half): vt[bh][d][m]
    vtrans_kernel<<<dim3(NN / 32, HD / 32, BB * HH), 256>>>(qkvh, vth);

    // 2) S[b,h] = scale * Q @ K^T : 32 x [1024,1024,128], fp32 out
    hgemm_kernel<false, false><<<dim3(NN / 128, NN / 128, BB * HH), 256, SMEM_BYTES>>>(
        qkvh, qkvh + CC, S, nullptr,
        HD, C3, C3, NN,
        HH,
        /*sAi*/ HD, /*sAo*/ (long long)NN * C3,
        /*sBi*/ HD, /*sBo*/ (long long)NN * C3,
        /*sCi*/ (long long)NN * NN, /*sCo*/ (long long)HH * NN * NN,
        SCALE);

    // 3) cross-head mix + softmax: S fp32 -> P fp16
    mix_softmax_kernel<<<BB * NN, 256>>>(S, P, w_main, w_rest);

    // 4) O[b,h] = P @ Vt^T : 32 x [1024,128,1024], fp16 out
    hgemm_kernel<true, false><<<dim3(HD / 128, NN / 128, BB * HH), 256, SMEM_BYTES>>>(
        P, vth, Oh, nullptr,
        NN, NN, NN, CC,
        HH,
        /*sAi*/ (long long)NN * NN, /*sAo*/ (long long)HH * NN * NN,
        /*sBi*/ (long long)HD * NN, /*sBo*/ (long long)HH * HD * NN,
        /*sCi*/ HD, /*sCo*/ (long long)NN * CC,
        1.0f);

    // 5) out = Oh @ Wproj_h^T + b : [8192,512,512], fp32 out + bias
    hgemm_kernel<false, true><<<dim3(CC / 128, BN_TOK / 128, 1), 256, SMEM_BYTES>>>(
        Oh, wph, out, b_proj,
        CC, CC, CC, CC,
        1, 0, 0, 0, 0, 0, 0, 1.0f);
}

// round 15
// speedup vs baseline: 1.7454x; 1.0872x over previous
#include <cuda_runtime.h>
#include <cuda_fp16.h>
#include <cstdint>

// Problem constants
#define BB   8
#define NN   1024
#define CC   512
#define HH   4
#define HD   128
#define BN_TOK (BB * NN)          // 8192
#define C3  (3 * CC)              // 1536
#define SCALE 0.08838834764831845f  // 128^-0.5

#define NST 3                      // pipeline stages
#define BK  32                     // k (halves) per stage
#define HPITCH 40                  // halves per row in smem tiles (32 + 8 pad)
#define STGH (128 * HPITCH)        // halves per operand stage
#define SMEM_BYTES (NST * 2 * STGH * 2)   // 61440

// Scratch (device globals: no allocation allowed)
__device__ __half g_qkvh[(size_t)BN_TOK * C3];        // QKV, fp16
__device__ float  g_s[(size_t)BB * HH * NN * NN];     // S scores fp32
__device__ __half g_p[(size_t)BB * HH * NN * NN];     // P = softmax(mix(S)), fp16
__device__ __half g_oh[(size_t)BN_TOK * CC];          // attention out, fp16
__device__ __half g_xh[(size_t)BN_TOK * CC];          // x fp16
__device__ __half g_wqh[(size_t)C3 * CC];             // w_qkv fp16
__device__ __half g_wph[(size_t)CC * CC];             // w_proj fp16
__device__ __half g_vth[(size_t)BB * HH * HD * NN];   // V transposed [bh][d][m], fp16

__device__ __forceinline__ void mma_f16(float* c, const unsigned* a, const unsigned* b) {
    asm volatile(
        "mma.sync.aligned.m16n8k16.row.col.f32.f16.f16.f32 "
        "{%0,%1,%2,%3}, {%4,%5,%6,%7}, {%8,%9}, {%0,%1,%2,%3};"
        : "+f"(c[0]), "+f"(c[1]), "+f"(c[2]), "+f"(c[3])
        : "r"(a[0]), "r"(a[1]), "r"(a[2]), "r"(a[3]), "r"(b[0]), "r"(b[1]));
}

__device__ __forceinline__ void ldsm_x4(
    unsigned& r0, unsigned& r1, unsigned& r2, unsigned& r3, uint32_t addr)
{
    asm volatile(
        "ldmatrix.sync.aligned.m8n8.x4.shared.b16 {%0,%1,%2,%3}, [%4];"
        : "=r"(r0), "=r"(r1), "=r"(r2), "=r"(r3) : "r"(addr));
}

__device__ __forceinline__ void cp16(unsigned dst, const void* src) {
    asm volatile("cp.async.cg.shared.global [%0], [%1], 16;" :: "r"(dst), "l"(src));
}
__device__ __forceinline__ void cp_commit() {
    asm volatile("cp.async.commit_group;");
}
__device__ __forceinline__ void cp_wait() {
    asm volatile("cp.async.wait_group %0;" :: "n"(NST - 2));
}

// ---------------------------------------------------------------------------
// fp16 convert prepass
// ---------------------------------------------------------------------------
__global__ __launch_bounds__(256) void tohalf_kernel(
    const float* __restrict__ in, __half* __restrict__ out, int n4)
{
    int i = blockIdx.x * 256 + threadIdx.x;
    if (i < n4) {
        float4 v = ((const float4*)in)[i];
        ((__half2*)out)[i * 2]     = __floats2half2_rn(v.x, v.y);
        ((__half2*)out)[i * 2 + 1] = __floats2half2_rn(v.z, v.w);
    }
}

// ---------------------------------------------------------------------------
// V transpose (half): vt[bh][d][m]
// ---------------------------------------------------------------------------
__global__ __launch_bounds__(256) void vtrans_kernel(
    const __half* __restrict__ qkv, __half* __restrict__ vt)
{
    __shared__ __half t[32][34];
    const int bh = blockIdx.z;
    const int b = bh / HH, h = bh % HH;
    const int m0 = blockIdx.x * 32;
    const int d0 = blockIdx.y * 32;
    const int lx = threadIdx.x & 31, ly = threadIdx.x >> 5;

    const __half* src = qkv + (size_t)b * NN * C3 + 2 * CC + h * HD;
    #pragma unroll
    for (int r = 0; r < 4; r++) {
        int m = m0 + ly + r * 8;
        t[ly + r * 8][lx] = src[(size_t)m * C3 + d0 + lx];
    }
    __syncthreads();
    __half* dst = vt + (size_t)bh * HD * NN;
    #pragma unroll
    for (int r = 0; r < 4; r++) {
        int d = d0 + ly + r * 8;
        dst[(size_t)d * NN + m0 + lx] = t[lx][ly + r * 8];
    }
}

// ---------------------------------------------------------------------------
// fp16 tensor-core GEMM (m16n8k16) with ldmatrix fragment loads.
// cp.async 3-stage pipeline, BK=32/stage, one barrier/stage, 2 CTAs/SM.
// Both operands K-major: C[m][n] = alpha * sum_k A[m][k]*B[n][k] (+bias)
// CTA tile 128x128, 8 warps, warp tile 32x64. Per k16-step:
//   2 LDSM.x4 (A) + 4 LDSM.x4 (B) + 16 HMMA   (was 24 scalar LDS)
// Pitch 40 halves (80B rows): LDSM row addrs hit banks 20r mod 32 -> all 32
// banks once per phase, conflict-free.
// ---------------------------------------------------------------------------
template<bool HALF_OUT, bool BIAS>
__global__ __launch_bounds__(256, 2) void hgemm_kernel(
    const __half* __restrict__ A, const __half* __restrict__ B,
    void* __restrict__ Cv, const float* __restrict__ bias,
    int K, int lda, int ldb, int ldc,
    int bin,
    long long sAi, long long sAo,
    long long sBi, long long sBo,
    long long sCi, long long sCo,
    float alpha)
{
    int z  = blockIdx.z;
    int zi = z % bin, zo = z / bin;
    A += (size_t)zi * sAi + (size_t)zo * sAo;
    B += (size_t)zi * sBi + (size_t)zo * sBo;

    extern __shared__ __half smph[];
    __half* AsAll = smph;                 // [NST][128][HPITCH]
    __half* BsAll = smph + NST * STGH;    // [NST][128][HPITCH]

    const int tid  = threadIdx.x;
    const int lane = tid & 31;
    const int g    = lane >> 2;
    const int tg   = lane & 3;
    const int wm   = (tid >> 5) & 3;
    const int wn   = tid >> 7;
    const int mbase = wm * 32;
    const int nbase = wn * 64;

    const int rowBase = blockIdx.y * 128;
    const int colBase = blockIdx.x * 128;

    // ldmatrix lane roles: matSel picks 8x8 matrix, rowSel picks row within it
    const int matSel = lane >> 3;       // 0..3
    const int rowSel = lane & 7;
    // A x4 (per mi): mats = (m0-7,k0-7),(m8-15,k0-7),(m0-7,k8-15),(m8-15,k8-15)
    int aoff[2];
    #pragma unroll
    for (int mi = 0; mi < 2; mi++)
        aoff[mi] = (mbase + mi * 16 + ((matSel & 1) << 3) + rowSel) * HPITCH
                 + ((matSel >> 1) << 3);
    // B x4 (per nj, covers ni=2nj,2nj+1):
    // mats = (n(2nj),k0-7),(n(2nj),k8-15),(n(2nj+1),k0-7),(n(2nj+1),k8-15)
    int boff[4];
    #pragma unroll
    for (int nj = 0; nj < 4; nj++)
        boff[nj] = (nbase + ((nj << 1) + (matSel >> 1)) * 8 + rowSel) * HPITCH
                 + ((matSel & 1) << 3);

    float acc[2][8][4];
    #pragma unroll
    for (int mi = 0; mi < 2; mi++)
        #pragma unroll
        for (int ni = 0; ni < 8; ni++)
            #pragma unroll
            for (int r = 0; r < 4; r++) acc[mi][ni][r] = 0.0f;

    // stage loader: 128 rows x 32 halves (64B) per operand
    auto loadStage = [&](int st, int kt) {
        __half* Ad = AsAll + st * STGH;
        #pragma unroll
        for (int r = 0; r < 2; r++) {
            int c   = r * 256 + tid;
            int row = c >> 2;
            int ch  = (c & 3) << 3;
            cp16((unsigned)__cvta_generic_to_shared(Ad + row * HPITCH + ch),
                 A + (size_t)(rowBase + row) * lda + kt + ch);
        }
        __half* Bd = BsAll + st * STGH;
        #pragma unroll
        for (int r = 0; r < 2; r++) {
            int c   = r * 256 + tid;
            int row = c >> 2;
            int ch  = (c & 3) << 3;
            cp16((unsigned)__cvta_generic_to_shared(Bd + row * HPITCH + ch),
                 B + (size_t)(colBase + row) * ldb + kt + ch);
        }
    };

    const int nk = K >> 5;
    loadStage(0, 0);
    cp_commit();
    if (nk > 1) loadStage(1, BK);
    cp_commit();

    int st = 0;
    for (int it = 0; it < nk; it++) {
        cp_wait();
        __syncthreads();

        int ktn = (it + NST - 1) << 5;
        int stn = st + NST - 1; if (stn >= NST) stn -= NST;
        if (ktn < K) loadStage(stn, ktn);
        cp_commit();

        const uint32_t aB = (uint32_t)__cvta_generic_to_shared(AsAll + st * STGH);
        const uint32_t bB = (uint32_t)__cvta_generic_to_shared(BsAll + st * STGH);
        #pragma unroll
        for (int ks = 0; ks < BK; ks += 16) {
            unsigned a[2][4], b[8][2];
            #pragma unroll
            for (int mi = 0; mi < 2; mi++)
                ldsm_x4(a[mi][0], a[mi][1], a[mi][2], a[mi][3],
                        aB + 2u * (aoff[mi] + ks));
            #pragma unroll
            for (int nj = 0; nj < 4; nj++)
                ldsm_x4(b[2*nj][0], b[2*nj][1], b[2*nj+1][0], b[2*nj+1][1],
                        bB + 2u * (boff[nj] + ks));
            #pragma unroll
            for (int mi = 0; mi < 2; mi++)
                #pragma unroll
                for (int ni = 0; ni < 8; ni++)
                    mma_f16(acc[mi][ni], a[mi], b[ni]);
        }

        st++; if (st >= NST) st = 0;
    }

    // ---- Epilogue ----
    if (HALF_OUT) {
        __half* C = (__half*)Cv + (size_t)zi * sCi + (size_t)zo * sCo;
        #pragma unroll
        for (int mi = 0; mi < 2; mi++) {
            #pragma unroll
            for (int ni = 0; ni < 8; ni++) {
                int row = rowBase + mbase + mi * 16 + g;
                int col = colBase + nbase + ni * 8 + tg * 2;
                __half2 h0 = __floats2half2_rn(alpha * acc[mi][ni][0],
                                               alpha * acc[mi][ni][1]);
                __half2 h1 = __floats2half2_rn(alpha * acc[mi][ni][2],
                                               alpha * acc[mi][ni][3]);
                *(__half2*)(C + (size_t)row * ldc + col)       = h0;
                *(__half2*)(C + (size_t)(row + 8) * ldc + col) = h1;
            }
        }
    } else {
        float* C = (float*)Cv + (size_t)zi * sCi + (size_t)zo * sCo;
        #pragma unroll
        for (int mi = 0; mi < 2; mi++) {
            #pragma unroll
            for (int ni = 0; ni < 8; ni++) {
                int row = rowBase + mbase + mi * 16 + g;
                int col = colBase + nbase + ni * 8 + tg * 2;
                float bx = 0.f, by = 0.f;
                if (BIAS) { bx = bias[col]; by = bias[col + 1]; }
                float2 v0, v1;
                v0.x = alpha * acc[mi][ni][0] + bx;
                v0.y = alpha * acc[mi][ni][1] + by;
                v1.x = alpha * acc[mi][ni][2] + bx;
                v1.y = alpha * acc[mi][ni][3] + by;
                *(float2*)(C + (size_t)row * ldc + col)       = v0;
                *(float2*)(C + (size_t)(row + 8) * ldc + col) = v1;
            }
        }
    }
}

// ---------------------------------------------------------------------------
// Cross-head mix + softmax: reads S fp32, writes P fp16.
// ---------------------------------------------------------------------------
__global__ __launch_bounds__(256) void mix_softmax_kernel(
    const float* __restrict__ S, __half* __restrict__ P,
    const float* __restrict__ w_main,
    const float* __restrict__ w_rest)
{
    __shared__ float Mm[16];
    __shared__ float redA[4][8];
    __shared__ float redB[4][8];

    const int b    = blockIdx.x / NN;
    const int n    = blockIdx.x % NN;
    const int tid  = threadIdx.x;
    const int lane = tid & 31;
    const int wrp  = tid >> 5;

    if (tid < 16) {
        int i = tid >> 2, j = tid & 3;
        Mm[tid] = (i == j) ? w_main[i]
                           : w_rest[i * (HH - 1) + (j < i ? j : j - 1)];
    }
    __syncthreads();

    const size_t base = ((size_t)b * HH * NN + n) * NN + tid * 4;

    float4 sv[HH];
    #pragma unroll
    for (int h = 0; h < HH; h++)
        sv[h] = *(const float4*)(S + base + (size_t)h * NN * NN);

    float4 v[HH];
    float mx[HH];
    #pragma unroll
    for (int i = 0; i < HH; i++) {
        float m0 = Mm[i*4+0], m1 = Mm[i*4+1], m2 = Mm[i*4+2], m3 = Mm[i*4+3];
        v[i].x = m0*sv[0].x + m1*sv[1].x + m2*sv[2].x + m3*sv[3].x;
        v[i].y = m0*sv[0].y + m1*sv[1].y + m2*sv[2].y + m3*sv[3].y;
        v[i].z = m0*sv[0].z + m1*sv[1].z + m2*sv[2].z + m3*sv[3].z;
        v[i].w = m0*sv[0].w + m1*sv[1].w + m2*sv[2].w + m3*sv[3].w;
        mx[i] = fmaxf(fmaxf(v[i].x, v[i].y), fmaxf(v[i].z, v[i].w));
        #pragma unroll
        for (int o = 16; o > 0; o >>= 1)
            mx[i] = fmaxf(mx[i], __shfl_xor_sync(0xffffffffu, mx[i], o));
    }
    if (lane == 0) {
        #pragma unroll
        for (int i = 0; i < HH; i++) redA[i][wrp] = mx[i];
    }
    __syncthreads();

    float sm[HH];
    #pragma unroll
    for (int i = 0; i < HH; i++) {
        float rmax = redA[i][0];
        #pragma unroll
        for (int w = 1; w < 8; w++) rmax = fmaxf(rmax, redA[i][w]);
        v[i].x = __expf(v[i].x - rmax);
        v[i].y = __expf(v[i].y - rmax);
        v[i].z = __expf(v[i].z - rmax);
        v[i].w = __expf(v[i].w - rmax);
        sm[i] = (v[i].x + v[i].y) + (v[i].z + v[i].w);
        #pragma unroll
        for (int o = 16; o > 0; o >>= 1)
            sm[i] += __shfl_xor_sync(0xffffffffu, sm[i], o);
    }
    if (lane == 0) {
        #pragma unroll
        for (int i = 0; i < HH; i++) redB[i][wrp] = sm[i];
    }
    __syncthreads();

    #pragma unroll
    for (int i = 0; i < HH; i++) {
        float rsum = redB[i][0];
        #pragma unroll
        for (int w = 1; w < 8; w++) rsum += redB[i][w];
        float inv = 1.0f / rsum;
        __half2 h0 = __floats2half2_rn(v[i].x * inv, v[i].y * inv);
        __half2 h1 = __floats2half2_rn(v[i].z * inv, v[i].w * inv);
        __half2* dst = (__half2*)(P + base + (size_t)i * NN * NN);
        dst[0] = h0;
        dst[1] = h1;
    }
}

// ---------------------------------------------------------------------------
extern "C" void kernel_launch(void* const* d_in, const int* in_sizes, int n_in,
                              void* d_out, int out_size)
{
    const float* x      = (const float*)d_in[0];  // [B,N,C]
    const float* w_qkv  = (const float*)d_in[1];  // [3C,C]
    const float* w_proj = (const float*)d_in[2];  // [C,C]
    const float* b_proj = (const float*)d_in[3];  // [C]
    const float* w_main = (const float*)d_in[4];  // [H]
    const float* w_rest = (const float*)d_in[5];  // [H,H-1]
    float* out = (float*)d_out;                   // [B,N,C]

    __half* qkvh; cudaGetSymbolAddress((void**)&qkvh, g_qkvh);
    float*  S;    cudaGetSymbolAddress((void**)&S,    g_s);
    __half* P;    cudaGetSymbolAddress((void**)&P,    g_p);
    __half* Oh;   cudaGetSymbolAddress((void**)&Oh,   g_oh);
    __half* xh;   cudaGetSymbolAddress((void**)&xh,   g_xh);
    __half* wqh;  cudaGetSymbolAddress((void**)&wqh,  g_wqh);
    __half* wph;  cudaGetSymbolAddress((void**)&wph,  g_wph);
    __half* vth;  cudaGetSymbolAddress((void**)&vth,  g_vth);

    cudaFuncSetAttribute(hgemm_kernel<true,  false>,
                         cudaFuncAttributeMaxDynamicSharedMemorySize, SMEM_BYTES);
    cudaFuncSetAttribute(hgemm_kernel<false, false>,
                         cudaFuncAttributeMaxDynamicSharedMemorySize, SMEM_BYTES);
    cudaFuncSetAttribute(hgemm_kernel<false, true >,
                         cudaFuncAttributeMaxDynamicSharedMemorySize, SMEM_BYTES);

    // 0) fp16 convert inputs
    tohalf_kernel<<<(BN_TOK * CC / 4) / 256, 256>>>(x, xh, BN_TOK * CC / 4);
    tohalf_kernel<<<(C3 * CC / 4) / 256, 256>>>(w_qkv, wqh, C3 * CC / 4);
    tohalf_kernel<<<(CC * CC / 4) / 256, 256>>>(w_proj, wph, CC * CC / 4);

    // 1) QKV = Xh @ Wqkv_h^T : [8192,1536,512], fp16 out
    hgemm_kernel<true, false><<<dim3(C3 / 128, BN_TOK / 128, 1), 256, SMEM_BYTES>>>(
        xh, wqh, qkvh, nullptr,
        CC, CC, CC, C3,
        1, 0, 0, 0, 0, 0, 0, 1.0f);

    // 1b) transpose V (half)
    vtrans_kernel<<<dim3(NN / 32, HD / 32, BB * HH), 256>>>(qkvh, vth);

    // 2) S[b,h] = scale * Q @ K^T : 32 x [1024,1024,128], fp32 out
    hgemm_kernel<false, false><<<dim3(NN / 128, NN / 128, BB * HH), 256, SMEM_BYTES>>>(
        qkvh, qkvh + CC, S, nullptr,
        HD, C3, C3, NN,
        HH,
        /*sAi*/ HD, /*sAo*/ (long long)NN * C3,
        /*sBi*/ HD, /*sBo*/ (long long)NN * C3,
        /*sCi*/ (long long)NN * NN, /*sCo*/ (long long)HH * NN * NN,
        SCALE);

    // 3) cross-head mix + softmax: S fp32 -> P fp16
    mix_softmax_kernel<<<BB * NN, 256>>>(S, P, w_main, w_rest);

    // 4) O[b,h] = P @ Vt^T : 32 x [1024,128,1024], fp16 out
    hgemm_kernel<true, false><<<dim3(HD / 128, NN / 128, BB * HH), 256, SMEM_BYTES>>>(
        P, vth, Oh, nullptr,
        NN, NN, NN, CC,
        HH,
        /*sAi*/ (long long)NN * NN, /*sAo*/ (long long)HH * NN * NN,
        /*sBi*/ (long long)HD * NN, /*sBo*/ (long long)HH * HD * NN,
        /*sCi*/ HD, /*sCo*/ (long long)NN * CC,
        1.0f);

    // 5) out = Oh @ Wproj_h^T + b : [8192,512,512], fp32 out + bias
    hgemm_kernel<false, true><<<dim3(CC / 128, BN_TOK / 128, 1), 256, SMEM_BYTES>>>(
        Oh, wph, out, b_proj,
        CC, CC, CC, CC,
        1, 0, 0, 0, 0, 0, 0, 1.0f);
}

// round 16
// speedup vs baseline: 1.7470x; 1.0009x over previous
#include <cuda_runtime.h>
#include <cuda_fp16.h>
#include <cstdint>

// Problem constants
#define BB   8
#define NN   1024
#define CC   512
#define HH   4
#define HD   128
#define BN_TOK (BB * NN)          // 8192
#define C3  (3 * CC)              // 1536
#define SCALE 0.08838834764831845f  // 128^-0.5

#define NST 4                      // pipeline stages
#define BK  32                     // k (halves) per stage
#define HPITCH 40                  // halves per row in smem tiles (32 + 8 pad)
#define STGH (128 * HPITCH)        // halves per operand stage
#define SMEM_BYTES (NST * 2 * STGH * 2)   // 81920

// Scratch (device globals: no allocation allowed)
__device__ __half g_qkvh[(size_t)BN_TOK * C3];        // QKV, fp16
__device__ __half g_s[(size_t)BB * HH * NN * NN];     // S scores fp16 -> P in-place
__device__ __half g_oh[(size_t)BN_TOK * CC];          // attention out, fp16
__device__ __half g_xh[(size_t)BN_TOK * CC];          // x fp16
__device__ __half g_wqh[(size_t)C3 * CC];             // w_qkv fp16
__device__ __half g_wph[(size_t)CC * CC];             // w_proj fp16
__device__ __half g_vth[(size_t)BB * HH * HD * NN];   // V transposed [bh][d][m], fp16

__device__ __forceinline__ void mma_f16(float* c, const unsigned* a, const unsigned* b) {
    asm volatile(
        "mma.sync.aligned.m16n8k16.row.col.f32.f16.f16.f32 "
        "{%0,%1,%2,%3}, {%4,%5,%6,%7}, {%8,%9}, {%0,%1,%2,%3};"
        : "+f"(c[0]), "+f"(c[1]), "+f"(c[2]), "+f"(c[3])
        : "r"(a[0]), "r"(a[1]), "r"(a[2]), "r"(a[3]), "r"(b[0]), "r"(b[1]));
}

__device__ __forceinline__ void ldsm_x4(
    unsigned& r0, unsigned& r1, unsigned& r2, unsigned& r3, uint32_t addr)
{
    asm volatile(
        "ldmatrix.sync.aligned.m8n8.x4.shared.b16 {%0,%1,%2,%3}, [%4];"
        : "=r"(r0), "=r"(r1), "=r"(r2), "=r"(r3) : "r"(addr));
}

__device__ __forceinline__ void cp16(unsigned dst, const void* src) {
    asm volatile("cp.async.cg.shared.global [%0], [%1], 16;" :: "r"(dst), "l"(src));
}
__device__ __forceinline__ void cp_commit() {
    asm volatile("cp.async.commit_group;");
}
__device__ __forceinline__ void cp_wait() {
    asm volatile("cp.async.wait_group %0;" :: "n"(NST - 2));
}

// ---------------------------------------------------------------------------
// fp16 convert prepass
// ---------------------------------------------------------------------------
__global__ __launch_bounds__(256) void tohalf_kernel(
    const float* __restrict__ in, __half* __restrict__ out, int n4)
{
    int i = blockIdx.x * 256 + threadIdx.x;
    if (i < n4) {
        float4 v = ((const float4*)in)[i];
        ((__half2*)out)[i * 2]     = __floats2half2_rn(v.x, v.y);
        ((__half2*)out)[i * 2 + 1] = __floats2half2_rn(v.z, v.w);
    }
}

// ---------------------------------------------------------------------------
// V transpose (half): vt[bh][d][m]
// ---------------------------------------------------------------------------
__global__ __launch_bounds__(256) void vtrans_kernel(
    const __half* __restrict__ qkv, __half* __restrict__ vt)
{
    __shared__ __half t[32][34];
    const int bh = blockIdx.z;
    const int b = bh / HH, h = bh % HH;
    const int m0 = blockIdx.x * 32;
    const int d0 = blockIdx.y * 32;
    const int lx = threadIdx.x & 31, ly = threadIdx.x >> 5;

    const __half* src = qkv + (size_t)b * NN * C3 + 2 * CC + h * HD;
    #pragma unroll
    for (int r = 0; r < 4; r++) {
        int m = m0 + ly + r * 8;
        t[ly + r * 8][lx] = src[(size_t)m * C3 + d0 + lx];
    }
    __syncthreads();
    __half* dst = vt + (size_t)bh * HD * NN;
    #pragma unroll
    for (int r = 0; r < 4; r++) {
        int d = d0 + ly + r * 8;
        dst[(size_t)d * NN + m0 + lx] = t[lx][ly + r * 8];
    }
}

// ---------------------------------------------------------------------------
// fp16 tensor-core GEMM (m16n8k16) with ldmatrix fragment loads.
// cp.async 4-stage pipeline, BK=32/stage, one barrier/stage, 2 CTAs/SM.
// Both operands K-major: C[m][n] = alpha * sum_k A[m][k]*B[n][k] (+bias)
// CTA tile 128x128, 8 warps, warp tile 32x64. Per k16-step:
//   2 LDSM.x4 (A) + 4 LDSM.x4 (B) + 16 HMMA
// Pitch 40 halves (80B rows): LDSM rows hit banks 20r mod 32 -> conflict-free.
// ---------------------------------------------------------------------------
template<bool HALF_OUT, bool BIAS>
__global__ __launch_bounds__(256, 2) void hgemm_kernel(
    const __half* __restrict__ A, const __half* __restrict__ B,
    void* __restrict__ Cv, const float* __restrict__ bias,
    int K, int lda, int ldb, int ldc,
    int bin,
    long long sAi, long long sAo,
    long long sBi, long long sBo,
    long long sCi, long long sCo,
    float alpha)
{
    int z  = blockIdx.z;
    int zi = z % bin, zo = z / bin;
    A += (size_t)zi * sAi + (size_t)zo * sAo;
    B += (size_t)zi * sBi + (size_t)zo * sBo;

    extern __shared__ __half smph[];
    __half* AsAll = smph;                 // [NST][128][HPITCH]
    __half* BsAll = smph + NST * STGH;    // [NST][128][HPITCH]

    const int tid  = threadIdx.x;
    const int lane = tid & 31;
    const int g    = lane >> 2;
    const int tg   = lane & 3;
    const int wm   = (tid >> 5) & 3;
    const int wn   = tid >> 7;
    const int mbase = wm * 32;
    const int nbase = wn * 64;

    const int rowBase = blockIdx.y * 128;
    const int colBase = blockIdx.x * 128;

    const int matSel = lane >> 3;       // 0..3
    const int rowSel = lane & 7;
    int aoff[2];
    #pragma unroll
    for (int mi = 0; mi < 2; mi++)
        aoff[mi] = (mbase + mi * 16 + ((matSel & 1) << 3) + rowSel) * HPITCH
                 + ((matSel >> 1) << 3);
    int boff[4];
    #pragma unroll
    for (int nj = 0; nj < 4; nj++)
        boff[nj] = (nbase + ((nj << 1) + (matSel >> 1)) * 8 + rowSel) * HPITCH
                 + ((matSel & 1) << 3);

    float acc[2][8][4];
    #pragma unroll
    for (int mi = 0; mi < 2; mi++)
        #pragma unroll
        for (int ni = 0; ni < 8; ni++)
            #pragma unroll
            for (int r = 0; r < 4; r++) acc[mi][ni][r] = 0.0f;

    auto loadStage = [&](int st, int kt) {
        __half* Ad = AsAll + st * STGH;
        #pragma unroll
        for (int r = 0; r < 2; r++) {
            int c   = r * 256 + tid;
            int row = c >> 2;
            int ch  = (c & 3) << 3;
            cp16((unsigned)__cvta_generic_to_shared(Ad + row * HPITCH + ch),
                 A + (size_t)(rowBase + row) * lda + kt + ch);
        }
        __half* Bd = BsAll + st * STGH;
        #pragma unroll
        for (int r = 0; r < 2; r++) {
            int c   = r * 256 + tid;
            int row = c >> 2;
            int ch  = (c & 3) << 3;
            cp16((unsigned)__cvta_generic_to_shared(Bd + row * HPITCH + ch),
                 B + (size_t)(colBase + row) * ldb + kt + ch);
        }
    };

    const int nk = K >> 5;   // all our K have nk >= 4
    loadStage(0, 0);        cp_commit();
    loadStage(1, BK);       cp_commit();
    loadStage(2, 2 * BK);   cp_commit();

    int st = 0;
    for (int it = 0; it < nk; it++) {
        cp_wait();
        __syncthreads();     // stage `st` complete+visible; all warps finished
                             // reading the stage refilled below (WAR safe)

        int ktn = (it + NST - 1) << 5;
        int stn = st + NST - 1; if (stn >= NST) stn -= NST;
        if (ktn < K) loadStage(stn, ktn);
        cp_commit();

        const uint32_t aB = (uint32_t)__cvta_generic_to_shared(AsAll + st * STGH);
        const uint32_t bB = (uint32_t)__cvta_generic_to_shared(BsAll + st * STGH);
        #pragma unroll
        for (int ks = 0; ks < BK; ks += 16) {
            unsigned a[2][4], b[8][2];
            #pragma unroll
            for (int mi = 0; mi < 2; mi++)
                ldsm_x4(a[mi][0], a[mi][1], a[mi][2], a[mi][3],
                        aB + 2u * (aoff[mi] + ks));
            #pragma unroll
            for (int nj = 0; nj < 4; nj++)
                ldsm_x4(b[2*nj][0], b[2*nj][1], b[2*nj+1][0], b[2*nj+1][1],
                        bB + 2u * (boff[nj] + ks));
            #pragma unroll
            for (int mi = 0; mi < 2; mi++)
                #pragma unroll
                for (int ni = 0; ni < 8; ni++)
                    mma_f16(acc[mi][ni], a[mi], b[ni]);
        }

        st++; if (st >= NST) st = 0;
    }

    // ---- Epilogue ----
    if (HALF_OUT) {
        __half* C = (__half*)Cv + (size_t)zi * sCi + (size_t)zo * sCo;
        #pragma unroll
        for (int mi = 0; mi < 2; mi++) {
            #pragma unroll
            for (int ni = 0; ni < 8; ni++) {
                int row = rowBase + mbase + mi * 16 + g;
                int col = colBase + nbase + ni * 8 + tg * 2;
                __half2 h0 = __floats2half2_rn(alpha * acc[mi][ni][0],
                                               alpha * acc[mi][ni][1]);
                __half2 h1 = __floats2half2_rn(alpha * acc[mi][ni][2],
                                               alpha * acc[mi][ni][3]);
                *(__half2*)(C + (size_t)row * ldc + col)       = h0;
                *(__half2*)(C + (size_t)(row + 8) * ldc + col) = h1;
            }
        }
    } else {
        float* C = (float*)Cv + (size_t)zi * sCi + (size_t)zo * sCo;
        #pragma unroll
        for (int mi = 0; mi < 2; mi++) {
            #pragma unroll
            for (int ni = 0; ni < 8; ni++) {
                int row = rowBase + mbase + mi * 16 + g;
                int col = colBase + nbase + ni * 8 + tg * 2;
                float bx = 0.f, by = 0.f;
                if (BIAS) { bx = bias[col]; by = bias[col + 1]; }
                float2 v0, v1;
                v0.x = alpha * acc[mi][ni][0] + bx;
                v0.y = alpha * acc[mi][ni][1] + by;
                v1.x = alpha * acc[mi][ni][2] + bx;
                v1.y = alpha * acc[mi][ni][3] + by;
                *(float2*)(C + (size_t)row * ldc + col)       = v0;
                *(float2*)(C + (size_t)(row + 8) * ldc + col) = v1;
            }
        }
    }
}

// ---------------------------------------------------------------------------
// Cross-head mix + softmax, in-place over fp16 S (reads S half, writes P half).
// One CTA per (b, n), 256 threads, 3 barriers, fp32 math in registers.
// ---------------------------------------------------------------------------
__global__ __launch_bounds__(256) void mix_softmax_kernel(
    __half* __restrict__ S,
    const float* __restrict__ w_main,
    const float* __restrict__ w_rest)
{
    __shared__ float Mm[16];
    __shared__ float redA[4][8];
    __shared__ float redB[4][8];

    const int b    = blockIdx.x / NN;
    const int n    = blockIdx.x % NN;
    const int tid  = threadIdx.x;
    const int lane = tid & 31;
    const int wrp  = tid >> 5;

    if (tid < 16) {
        int i = tid >> 2, j = tid & 3;
        Mm[tid] = (i == j) ? w_main[i]
                           : w_rest[i * (HH - 1) + (j < i ? j : j - 1)];
    }
    __syncthreads();

    const size_t base = ((size_t)b * HH * NN + n) * NN + tid * 4;

    float4 sv[HH];
    #pragma unroll
    for (int h = 0; h < HH; h++) {
        const __half2* p = (const __half2*)(S + base + (size_t)h * NN * NN);
        float2 f0 = __half22float2(p[0]);
        float2 f1 = __half22float2(p[1]);
        sv[h] = make_float4(f0.x, f0.y, f1.x, f1.y);
    }

    float4 v[HH];
    float mx[HH];
    #pragma unroll
    for (int i = 0; i < HH; i++) {
        float m0 = Mm[i*4+0], m1 = Mm[i*4+1], m2 = Mm[i*4+2], m3 = Mm[i*4+3];
        v[i].x = m0*sv[0].x + m1*sv[1].x + m2*sv[2].x + m3*sv[3].x;
        v[i].y = m0*sv[0].y + m1*sv[1].y + m2*sv[2].y + m3*sv[3].y;
        v[i].z = m0*sv[0].z + m1*sv[1].z + m2*sv[2].z + m3*sv[3].z;
        v[i].w = m0*sv[0].w + m1*sv[1].w + m2*sv[2].w + m3*sv[3].w;
        mx[i] = fmaxf(fmaxf(v[i].x, v[i].y), fmaxf(v[i].z, v[i].w));
        #pragma unroll
        for (int o = 16; o > 0; o >>= 1)
            mx[i] = fmaxf(mx[i], __shfl_xor_sync(0xffffffffu, mx[i], o));
    }
    if (lane == 0) {
        #pragma unroll
        for (int i = 0; i < HH; i++) redA[i][wrp] = mx[i];
    }
    __syncthreads();

    float sm[HH];
    #pragma unroll
    for (int i = 0; i < HH; i++) {
        float rmax = redA[i][0];
        #pragma unroll
        for (int w = 1; w < 8; w++) rmax = fmaxf(rmax, redA[i][w]);
        v[i].x = __expf(v[i].x - rmax);
        v[i].y = __expf(v[i].y - rmax);
        v[i].z = __expf(v[i].z - rmax);
        v[i].w = __expf(v[i].w - rmax);
        sm[i] = (v[i].x + v[i].y) + (v[i].z + v[i].w);
        #pragma unroll
        for (int o = 16; o > 0; o >>= 1)
            sm[i] += __shfl_xor_sync(0xffffffffu, sm[i], o);
    }
    if (lane == 0) {
        #pragma unroll
        for (int i = 0; i < HH; i++) redB[i][wrp] = sm[i];
    }
    __syncthreads();

    #pragma unroll
    for (int i = 0; i < HH; i++) {
        float rsum = redB[i][0];
        #pragma unroll
        for (int w = 1; w < 8; w++) rsum += redB[i][w];
        float inv = 1.0f / rsum;
        __half2 h0 = __floats2half2_rn(v[i].x * inv, v[i].y * inv);
        __half2 h1 = __floats2half2_rn(v[i].z * inv, v[i].w * inv);
        __half2* dst = (__half2*)(S + base + (size_t)i * NN * NN);
        dst[0] = h0;
        dst[1] = h1;
    }
}

// ---------------------------------------------------------------------------
extern "C" void kernel_launch(void* const* d_in, const int* in_sizes, int n_in,
                              void* d_out, int out_size)
{
    const float* x      = (const float*)d_in[0];  // [B,N,C]
    const float* w_qkv  = (const float*)d_in[1];  // [3C,C]
    const float* w_proj = (const float*)d_in[2];  // [C,C]
    const float* b_proj = (const float*)d_in[3];  // [C]
    const float* w_main = (const float*)d_in[4];  // [H]
    const float* w_rest = (const float*)d_in[5];  // [H,H-1]
    float* out = (float*)d_out;                   // [B,N,C]

    __half* qkvh; cudaGetSymbolAddress((void**)&qkvh, g_qkvh);
    __half* S;    cudaGetSymbolAddress((void**)&S,    g_s);
    __half* Oh;   cudaGetSymbolAddress((void**)&Oh,   g_oh);
    __half* xh;   cudaGetSymbolAddress((void**)&xh,   g_xh);
    __half* wqh;  cudaGetSymbolAddress((void**)&wqh,  g_wqh);
    __half* wph;  cudaGetSymbolAddress((void**)&wph,  g_wph);
    __half* vth;  cudaGetSymbolAddress((void**)&vth,  g_vth);

    cudaFuncSetAttribute(hgemm_kernel<true,  false>,
                         cudaFuncAttributeMaxDynamicSharedMemorySize, SMEM_BYTES);
    cudaFuncSetAttribute(hgemm_kernel<false, true >,
                         cudaFuncAttributeMaxDynamicSharedMemorySize, SMEM_BYTES);

    // 0) fp16 convert inputs
    tohalf_kernel<<<(BN_TOK * CC / 4) / 256, 256>>>(x, xh, BN_TOK * CC / 4);
    tohalf_kernel<<<(C3 * CC / 4) / 256, 256>>>(w_qkv, wqh, C3 * CC / 4);
    tohalf_kernel<<<(CC * CC / 4) / 256, 256>>>(w_proj, wph, CC * CC / 4);

    // 1) QKV = Xh @ Wqkv_h^T : [8192,1536,512], fp16 out
    hgemm_kernel<true, false><<<dim3(C3 / 128, BN_TOK / 128, 1), 256, SMEM_BYTES>>>(
        xh, wqh, qkvh, nullptr,
        CC, CC, CC, C3,
        1, 0, 0, 0, 0, 0, 0, 1.0f);

    // 1b) transpose V (half)
    vtrans_kernel<<<dim3(NN / 32, HD / 32, BB * HH), 256>>>(qkvh, vth);

    // 2) S[b,h] = scale * Q @ K^T : 32 x [1024,1024,128], fp16 out
    hgemm_kernel<true, false><<<dim3(NN / 128, NN / 128, BB * HH), 256, SMEM_BYTES>>>(
        qkvh, qkvh + CC, S, nullptr,
        HD, C3, C3, NN,
        HH,
        /*sAi*/ HD, /*sAo*/ (long long)NN * C3,
        /*sBi*/ HD, /*sBo*/ (long long)NN * C3,
        /*sCi*/ (long long)NN * NN, /*sCo*/ (long long)HH * NN * NN,
        SCALE);

    // 3) cross-head mix + softmax, in-place fp16
    mix_softmax_kernel<<<BB * NN, 256>>>(S, w_main, w_rest);

    // 4) O[b,h] = P @ Vt^T : 32 x [1024,128,1024], fp16 out
    hgemm_kernel<true, false><<<dim3(HD / 128, NN / 128, BB * HH), 256, SMEM_BYTES>>>(
        S, vth, Oh, nullptr,
        NN, NN, NN, CC,
        HH,
        /*sAi*/ (long long)NN * NN, /*sAo*/ (long long)HH * NN * NN,
        /*sBi*/ (long long)HD * NN, /*sBo*/ (long long)HH * HD * NN,
        /*sCi*/ HD, /*sCo*/ (long long)NN * CC,
        1.0f);

    // 5) out = Oh @ Wproj_h^T + b : [8192,512,512], fp32 out + bias
    hgemm_kernel<false, true><<<dim3(CC / 128, BN_TOK / 128, 1), 256, SMEM_BYTES>>>(
        Oh, wph, out, b_proj,
        CC, CC, CC, CC,
        1, 0, 0, 0, 0, 0, 0, 1.0f);
}